// round 14
// baseline (speedup 1.0000x reference)
#include <cuda_runtime.h>

// stepSSM fused kernel, R13: R3 body + forced occupancy via launch bounds.
//
// Evidence: single-node variants all settle at 46-47 regs / occ 53% / DRAM
// ~75% (R3, R12 — source-level tricks incl. volatile-asm LDS didn't move
// ptxas). The 80us-class kernels (R6/R11) differ only in occupancy (32 regs,
// 85%), but need const-bank memcpy nodes costing ~3.5us each at replay.
//
// Fix: __launch_bounds__(256, 7) caps regs at 36 and guarantees 7 blocks/SM
// (1792 thr = 87% occ). ptxas satisfies the cap by REMATERIALIZING
// shared-memory loads (re-reading weights from smem at use sites) instead of
// keeping a hoisted weight cache live — shared reload, not local spill, is
// its preferred remedy for shared-sourced values.
//
// Layout (proven R3): scalar smem consts (broadcast LDS), 4 threads/row,
// fully coalesced float4 streaming state I/O, quad shfl reductions.
//
// Inputs (metadata order):
//   0: x[B,4]  1: states[4,B,2,4,2]  2: fc1_w[2,4]  3: fc1_b[2]
//   4: fc_w[5,2,2]  5: fc_b[5,2]  6: A[4,2,4,2]  7: Bm[4,2,4,2]
//   8: C[4,1,2,4,2]  9: D[4,1,2]
// Output: h[B,2] ++ new_states[4,B,2,4,2]  (f32)

#define THREADS 256

#define OFF_FC1W 0    // 8
#define OFF_FC1B 8    // 2
#define OFF_FCW  10   // 20
#define OFF_FCB  30   // 10
#define OFF_A    40   // 64
#define OFF_BM   104  // 64
#define OFF_C    168  // 64
#define OFF_D    232  // 8
#define N_CONST  240

__global__ __launch_bounds__(THREADS, 7) void step_ssm_kernel(
    const float4* __restrict__ x,        // [B]
    const float4* __restrict__ states,   // [4*B*4] float4
    const float*  __restrict__ fc1_w,
    const float*  __restrict__ fc1_b,
    const float*  __restrict__ fc_w,
    const float*  __restrict__ fc_b,
    const float*  __restrict__ A,
    const float*  __restrict__ Bm,
    const float*  __restrict__ C,
    const float*  __restrict__ D,
    float2*       __restrict__ out_h,      // [B]
    float4*       __restrict__ out_states, // [4*B*4] float4
    int B)
{
    __shared__ float sc[N_CONST];
    {
        int t = threadIdx.x;
        if (t < N_CONST) {
            float v;
            if      (t < OFF_FC1B) v = fc1_w[t - OFF_FC1W];
            else if (t < OFF_FCW)  v = fc1_b[t - OFF_FC1B];
            else if (t < OFF_FCB)  v = fc_w [t - OFF_FCW];
            else if (t < OFF_A)    v = fc_b [t - OFF_FCB];
            else if (t < OFF_BM)   v = A    [t - OFF_A];
            else if (t < OFF_C)    v = Bm   [t - OFF_BM];
            else if (t < OFF_D)    v = C    [t - OFF_C];
            else                   v = D    [t - OFF_D];
            sc[t] = v;
        }
    }
    __syncthreads();

    const int t   = blockIdx.x * blockDim.x + threadIdx.x;
    const int row = t >> 2;
    const int q   = t & 3;
    if (row >= B) return;

    const size_t layer_str = (size_t)B * 4;   // float4 units
    const size_t my_off    = (size_t)row * 4 + q;

    // front-load all global reads (MLP = 5)
    float4 st[4];
#pragma unroll
    for (int i = 0; i < 4; i++)
        st[i] = __ldcs(states + (size_t)i * layer_str + my_off);
    float4 xv = __ldg(x + row);

    // fc1 (replicated across the quad)
    float h0 = fmaf(xv.x, sc[OFF_FC1W + 0], fmaf(xv.y, sc[OFF_FC1W + 1],
               fmaf(xv.z, sc[OFF_FC1W + 2], fmaf(xv.w, sc[OFF_FC1W + 3], sc[OFF_FC1B + 0]))));
    float h1 = fmaf(xv.x, sc[OFF_FC1W + 4], fmaf(xv.y, sc[OFF_FC1W + 5],
               fmaf(xv.z, sc[OFF_FC1W + 6], fmaf(xv.w, sc[OFF_FC1W + 7], sc[OFF_FC1B + 1]))));

    const int hd = q >> 1;
    const int kq = q * 4;

#pragma unroll
    for (int i = 0; i < 4; i++) {
        const int lb = i * 16 + kq;
        const float u = (hd == 0) ? h0 : h1;

        float Ar0 = sc[OFF_A  + lb + 0], Ai0 = sc[OFF_A  + lb + 1];
        float Ar1 = sc[OFF_A  + lb + 2], Ai1 = sc[OFF_A  + lb + 3];
        float Br0 = sc[OFF_BM + lb + 0], Bi0 = sc[OFF_BM + lb + 1];
        float Br1 = sc[OFF_BM + lb + 2], Bi1 = sc[OFF_BM + lb + 3];
        float Cr0 = sc[OFF_C  + lb + 0], Ci0 = sc[OFF_C  + lb + 1];
        float Cr1 = sc[OFF_C  + lb + 2], Ci1 = sc[OFF_C  + lb + 3];

        float nr0 = fmaf(Ar0, st[i].x, fmaf(-Ai0, st[i].y, Br0 * u));
        float ni0 = fmaf(Ar0, st[i].y, fmaf( Ai0, st[i].x, Bi0 * u));
        float nr1 = fmaf(Ar1, st[i].z, fmaf(-Ai1, st[i].w, Br1 * u));
        float ni1 = fmaf(Ar1, st[i].w, fmaf( Ai1, st[i].z, Bi1 * u));

        __stcs(out_states + (size_t)i * layer_str + my_off,
               make_float4(nr0, ni0, nr1, ni1));

        // partial C-projection (2 f's), reduce within head pair, swap heads
        float acc = fmaf(Cr0, nr0, fmaf(-Ci0, ni0,
                    fmaf(Cr1, nr1, -Ci1 * ni1)));
        acc += __shfl_xor_sync(0xFFFFFFFFu, acc, 1);

        float y = fmaf(2.0f, acc, u * sc[OFF_D + i * 2 + hd]);
        y = (y >= 0.0f) ? y : 0.125f * y;
        float yo = __shfl_xor_sync(0xFFFFFFFFu, y, 2);
        float y0 = (hd == 0) ? y  : yo;
        float y1 = (hd == 0) ? yo : y;

        const int wb = OFF_FCW + i * 4;
        h0 = fmaf(y0, sc[wb + 0], fmaf(y1, sc[wb + 1], sc[OFF_FCB + i * 2 + 0]));
        h1 = fmaf(y0, sc[wb + 2], fmaf(y1, sc[wb + 3], sc[OFF_FCB + i * 2 + 1]));
    }

    // fc10 — lane q==0 writes the contiguous float2
    if (q == 0) {
        const int wb = OFF_FCW + 16;
        float o0 = fmaf(h0, sc[wb + 0], fmaf(h1, sc[wb + 1], sc[OFF_FCB + 8]));
        float o1 = fmaf(h0, sc[wb + 2], fmaf(h1, sc[wb + 3], sc[OFF_FCB + 9]));
        out_h[row] = make_float2(o0, o1);
    }
}

extern "C" void kernel_launch(void* const* d_in, const int* in_sizes, int n_in,
                              void* d_out, int out_size)
{
    const float* x     = (const float*)d_in[0];
    const float* states= (const float*)d_in[1];
    const float* fc1_w = (const float*)d_in[2];
    const float* fc1_b = (const float*)d_in[3];
    const float* fc_w  = (const float*)d_in[4];
    const float* fc_b  = (const float*)d_in[5];
    const float* A     = (const float*)d_in[6];
    const float* Bm    = (const float*)d_in[7];
    const float* C     = (const float*)d_in[8];
    const float* D     = (const float*)d_in[9];

    int B = in_sizes[0] / 4;  // x is [B,4]

    float*  out = (float*)d_out;
    float2* oh  = (float2*)out;                   // h: [B,2]
    float4* ost = (float4*)(out + (size_t)2 * B); // new_states: [4,B,2,4,2]

    long long total = (long long)B * 4;           // 4 threads per row
    int grid = (int)((total + THREADS - 1) / THREADS);
    step_ssm_kernel<<<grid, THREADS>>>(
        (const float4*)x, (const float4*)states,
        fc1_w, fc1_b, fc_w, fc_b, A, Bm, C, D,
        oh, ost, B);
}

// round 15
// speedup vs baseline: 1.0056x; 1.0056x over previous
#include <cuda_runtime.h>

// stepSSM fused kernel, R14: 2 rows per thread — amortize the weight traffic.
//
// Model (10 kernels measured): fast needs BOTH high warps-in-flight AND low
// l1tex share; at 1 row/thread those trade off (weight cache in GPRs -> occ
// 54%; remat via LDS -> L1 76%). Processing rows r and r+B/2 in one thread
// halves the per-row LDS/shfl/chain cost (weights read once, used twice),
// bringing l1tex wf/row to ~R11-kernel levels with ZERO extra graph nodes,
// while 10 outstanding state loads/thread compensate the lower occupancy.
//
// Both row streams stay perfectly coalesced (4 threads/row, consecutive
// lanes -> consecutive float4s in each half of the row space).
//
// Inputs (metadata order):
//   0: x[B,4]  1: states[4,B,2,4,2]  2: fc1_w[2,4]  3: fc1_b[2]
//   4: fc_w[5,2,2]  5: fc_b[5,2]  6: A[4,2,4,2]  7: Bm[4,2,4,2]
//   8: C[4,1,2,4,2]  9: D[4,1,2]
// Output: h[B,2] ++ new_states[4,B,2,4,2]  (f32)

#define THREADS 256

#define OFF_FC1W 0    // 8
#define OFF_FC1B 8    // 2
#define OFF_FCW  10   // 20
#define OFF_FCB  30   // 10
#define OFF_A    40   // 64
#define OFF_BM   104  // 64
#define OFF_C    168  // 64
#define OFF_D    232  // 8
#define N_CONST  240

__global__ __launch_bounds__(THREADS, 4) void step_ssm_kernel(
    const float4* __restrict__ x,        // [B]
    const float4* __restrict__ states,   // [4*B*4] float4
    const float*  __restrict__ fc1_w,
    const float*  __restrict__ fc1_b,
    const float*  __restrict__ fc_w,
    const float*  __restrict__ fc_b,
    const float*  __restrict__ A,
    const float*  __restrict__ Bm,
    const float*  __restrict__ C,
    const float*  __restrict__ D,
    float2*       __restrict__ out_h,      // [B]
    float4*       __restrict__ out_states, // [4*B*4] float4
    int B)
{
    __shared__ float sc[N_CONST];
    {
        int t = threadIdx.x;
        if (t < N_CONST) {
            float v;
            if      (t < OFF_FC1B) v = fc1_w[t - OFF_FC1W];
            else if (t < OFF_FCW)  v = fc1_b[t - OFF_FC1B];
            else if (t < OFF_FCB)  v = fc_w [t - OFF_FCW];
            else if (t < OFF_A)    v = fc_b [t - OFF_FCB];
            else if (t < OFF_BM)   v = A    [t - OFF_A];
            else if (t < OFF_C)    v = Bm   [t - OFF_BM];
            else if (t < OFF_D)    v = C    [t - OFF_C];
            else                   v = D    [t - OFF_D];
            sc[t] = v;
        }
    }
    __syncthreads();

    const int t    = blockIdx.x * blockDim.x + threadIdx.x;
    const int row  = t >> 2;
    const int q    = t & 3;
    const int half = B >> 1;
    if (row >= half) return;

    const size_t layer_str = (size_t)B * 4;          // float4 units
    const size_t off0      = (size_t)row * 4 + q;    // row r
    const size_t off1      = off0 + (size_t)half * 4;// row r + B/2

    // ---- front-load all global reads (MLP = 10) ----
    float4 s0[4], s1[4];
#pragma unroll
    for (int i = 0; i < 4; i++) {
        s0[i] = __ldcs(states + (size_t)i * layer_str + off0);
        s1[i] = __ldcs(states + (size_t)i * layer_str + off1);
    }
    float4 xv0 = __ldg(x + row);
    float4 xv1 = __ldg(x + row + half);

    // fc1 for both rows (weights read once)
    float a0, a1, a2, a3, a4;
    a0 = sc[OFF_FC1W + 0]; a1 = sc[OFF_FC1W + 1]; a2 = sc[OFF_FC1W + 2];
    a3 = sc[OFF_FC1W + 3]; a4 = sc[OFF_FC1B + 0];
    float h00 = fmaf(xv0.x, a0, fmaf(xv0.y, a1, fmaf(xv0.z, a2, fmaf(xv0.w, a3, a4))));
    float h10 = fmaf(xv1.x, a0, fmaf(xv1.y, a1, fmaf(xv1.z, a2, fmaf(xv1.w, a3, a4))));
    a0 = sc[OFF_FC1W + 4]; a1 = sc[OFF_FC1W + 5]; a2 = sc[OFF_FC1W + 6];
    a3 = sc[OFF_FC1W + 7]; a4 = sc[OFF_FC1B + 1];
    float h01 = fmaf(xv0.x, a0, fmaf(xv0.y, a1, fmaf(xv0.z, a2, fmaf(xv0.w, a3, a4))));
    float h11 = fmaf(xv1.x, a0, fmaf(xv1.y, a1, fmaf(xv1.z, a2, fmaf(xv1.w, a3, a4))));

    const int hd = q >> 1;
    const int kq = q * 4;

#pragma unroll
    for (int i = 0; i < 4; i++) {
        const int lb = i * 16 + kq;

        // layer constants read once, used for both rows
        float Ar0 = sc[OFF_A  + lb + 0], Ai0 = sc[OFF_A  + lb + 1];
        float Ar1 = sc[OFF_A  + lb + 2], Ai1 = sc[OFF_A  + lb + 3];
        float Br0 = sc[OFF_BM + lb + 0], Bi0 = sc[OFF_BM + lb + 1];
        float Br1 = sc[OFF_BM + lb + 2], Bi1 = sc[OFF_BM + lb + 3];
        float Cr0 = sc[OFF_C  + lb + 0], Ci0 = sc[OFF_C  + lb + 1];
        float Cr1 = sc[OFF_C  + lb + 2], Ci1 = sc[OFF_C  + lb + 3];
        float dd  = sc[OFF_D + i * 2 + hd];

        const float u0 = (hd == 0) ? h00 : h01;
        const float u1 = (hd == 0) ? h10 : h11;

        // row 0 state update + store
        float nr00 = fmaf(Ar0, s0[i].x, fmaf(-Ai0, s0[i].y, Br0 * u0));
        float ni00 = fmaf(Ar0, s0[i].y, fmaf( Ai0, s0[i].x, Bi0 * u0));
        float nr01 = fmaf(Ar1, s0[i].z, fmaf(-Ai1, s0[i].w, Br1 * u0));
        float ni01 = fmaf(Ar1, s0[i].w, fmaf( Ai1, s0[i].z, Bi1 * u0));
        __stcs(out_states + (size_t)i * layer_str + off0,
               make_float4(nr00, ni00, nr01, ni01));

        // row 1 state update + store
        float nr10 = fmaf(Ar0, s1[i].x, fmaf(-Ai0, s1[i].y, Br0 * u1));
        float ni10 = fmaf(Ar0, s1[i].y, fmaf( Ai0, s1[i].x, Bi0 * u1));
        float nr11 = fmaf(Ar1, s1[i].z, fmaf(-Ai1, s1[i].w, Br1 * u1));
        float ni11 = fmaf(Ar1, s1[i].w, fmaf( Ai1, s1[i].z, Bi1 * u1));
        __stcs(out_states + (size_t)i * layer_str + off1,
               make_float4(nr10, ni10, nr11, ni11));

        // C-projections, quad reductions (per row), head swap
        float ac0 = fmaf(Cr0, nr00, fmaf(-Ci0, ni00, fmaf(Cr1, nr01, -Ci1 * ni01)));
        float ac1 = fmaf(Cr0, nr10, fmaf(-Ci0, ni10, fmaf(Cr1, nr11, -Ci1 * ni11)));
        ac0 += __shfl_xor_sync(0xFFFFFFFFu, ac0, 1);
        ac1 += __shfl_xor_sync(0xFFFFFFFFu, ac1, 1);

        float yA = fmaf(2.0f, ac0, u0 * dd);
        float yB = fmaf(2.0f, ac1, u1 * dd);
        yA = (yA >= 0.0f) ? yA : 0.125f * yA;
        yB = (yB >= 0.0f) ? yB : 0.125f * yB;
        float yAo = __shfl_xor_sync(0xFFFFFFFFu, yA, 2);
        float yBo = __shfl_xor_sync(0xFFFFFFFFu, yB, 2);
        float y00 = (hd == 0) ? yA  : yAo;   // row0 head0
        float y01 = (hd == 0) ? yAo : yA;    // row0 head1
        float y10 = (hd == 0) ? yB  : yBo;
        float y11 = (hd == 0) ? yBo : yB;

        // fc_i (weights read once, applied to both rows)
        const int wb = OFF_FCW + i * 4;
        float w0 = sc[wb + 0], w1 = sc[wb + 1], w2 = sc[wb + 2], w3 = sc[wb + 3];
        float f0 = sc[OFF_FCB + i * 2 + 0], f1 = sc[OFF_FCB + i * 2 + 1];
        h00 = fmaf(y00, w0, fmaf(y01, w1, f0));
        h01 = fmaf(y00, w2, fmaf(y01, w3, f1));
        h10 = fmaf(y10, w0, fmaf(y11, w1, f0));
        h11 = fmaf(y10, w2, fmaf(y11, w3, f1));
    }

    // fc10 for both rows — lane q==0 writes contiguous float2s
    if (q == 0) {
        const int wb = OFF_FCW + 16;
        float w0 = sc[wb + 0], w1 = sc[wb + 1], w2 = sc[wb + 2], w3 = sc[wb + 3];
        float f0 = sc[OFF_FCB + 8], f1 = sc[OFF_FCB + 9];
        out_h[row]        = make_float2(fmaf(h00, w0, fmaf(h01, w1, f0)),
                                        fmaf(h00, w2, fmaf(h01, w3, f1)));
        out_h[row + half] = make_float2(fmaf(h10, w0, fmaf(h11, w1, f0)),
                                        fmaf(h10, w2, fmaf(h11, w3, f1)));
    }
}

extern "C" void kernel_launch(void* const* d_in, const int* in_sizes, int n_in,
                              void* d_out, int out_size)
{
    const float* x     = (const float*)d_in[0];
    const float* states= (const float*)d_in[1];
    const float* fc1_w = (const float*)d_in[2];
    const float* fc1_b = (const float*)d_in[3];
    const float* fc_w  = (const float*)d_in[4];
    const float* fc_b  = (const float*)d_in[5];
    const float* A     = (const float*)d_in[6];
    const float* Bm    = (const float*)d_in[7];
    const float* C     = (const float*)d_in[8];
    const float* D     = (const float*)d_in[9];

    int B = in_sizes[0] / 4;  // x is [B,4]

    float*  out = (float*)d_out;
    float2* oh  = (float2*)out;                   // h: [B,2]
    float4* ost = (float4*)(out + (size_t)2 * B); // new_states: [4,B,2,4,2]

    long long total = ((long long)B / 2) * 4;     // 4 threads per row-pair
    int grid = (int)((total + THREADS - 1) / THREADS);
    step_ssm_kernel<<<grid, THREADS>>>(
        (const float4*)x, (const float4*)states,
        fc1_w, fc1_b, fc_w, fc_b, A, Bm, C, D,
        oh, ost, B);
}